// round 7
// baseline (speedup 1.0000x reference)
#include <cuda_runtime.h>
#include <math.h>

// ---------------------------------------------------------------------------
// SwinTransformerBlock3D — fp32, f32x2 FMA, smem-staged weights w/ reg prefetch
// 2 kernels: A = LN1+gather+QKV+attn+proj+residual, B = LN2+MLP+residual
// ---------------------------------------------------------------------------

#define LTOK (16*64*64)
#define BATCH 2
#define C 96
#define NH 6
#define HD 16
#define NW 64
#define MLPH 384
#define NTILE 2048

typedef unsigned long long u64t;

__device__ float g_ybuf[(size_t)BATCH * LTOK * C];

// ---------------- helpers --------------------------------------------------
__device__ __forceinline__ unsigned sp(const void* p) {
    return (unsigned)__cvta_generic_to_shared(p);
}
__device__ __forceinline__ u64t ldsb64(const float* p) {
    u64t v; asm volatile("ld.shared.b64 %0,[%1];" : "=l"(v) : "r"(sp(p))); return v;
}
__device__ __forceinline__ void ldsv2b64(u64t& a, u64t& b, const float* p) {
    asm volatile("ld.shared.v2.b64 {%0,%1},[%2];" : "=l"(a), "=l"(b) : "r"(sp(p)));
}
__device__ __forceinline__ float2 ldsf2(const float* p) {
    float2 r; asm volatile("ld.shared.v2.f32 {%0,%1},[%2];"
                           : "=f"(r.x), "=f"(r.y) : "r"(sp(p))); return r;
}
__device__ __forceinline__ float4 ldsf4(const float* p) {
    float4 r; asm volatile("ld.shared.v4.f32 {%0,%1,%2,%3},[%4];"
                           : "=f"(r.x),"=f"(r.y),"=f"(r.z),"=f"(r.w) : "r"(sp(p))); return r;
}
__device__ __forceinline__ void stsb64(float* p, u64t v) {
    asm volatile("st.shared.b64 [%0],%1;" :: "r"(sp(p)), "l"(v));
}
__device__ __forceinline__ u64t pk2(float x, float y) {
    u64t r; asm("mov.b64 %0,{%1,%2};" : "=l"(r) : "f"(x), "f"(y)); return r;
}
__device__ __forceinline__ u64t dup2(float x) { return pk2(x, x); }
__device__ __forceinline__ float2 up2(u64t v) {
    float2 r; asm("mov.b64 {%0,%1},%2;" : "=f"(r.x), "=f"(r.y) : "l"(v)); return r;
}
__device__ __forceinline__ void fma2(u64t& d, u64t a, u64t b) {
    asm("fma.rn.f32x2 %0,%1,%2,%0;" : "+l"(d) : "l"(a), "l"(b));
}

// kernel A smem (float offsets)
#define A_XD   0        // xdup [96][130] dup pairs; reused as oT [96][68]
#define A_Q    12480    // qbuf [64][100]; reused as proj red [64][98]
#define A_KT   18880    // kT [96][68]
#define A_V    25408    // vbuf [64][100]
#define A_S    31808    // sbuf [64][68]
#define A_BIAS 36160    // 2058
#define A_REL  38218    // u16[4096]
#define A_SRC  40266    // int[64]
#define A_WB   40336    // weight chunk buf [9216] (QKV chunks / proj full)
#define A_TOT  49552

// ===========================================================================
// Kernel A
// ===========================================================================
__global__ __launch_bounds__(512, 1)
void win_attn_kernel(const float* __restrict__ x,
                     const float* __restrict__ g1, const float* __restrict__ b1,
                     const float* __restrict__ qkv_w, const float* __restrict__ qkv_b,
                     const float* __restrict__ proj_w, const float* __restrict__ proj_b,
                     const float* __restrict__ bias_table)
{
    extern __shared__ float smf[];
    float* xdup = smf + A_XD;
    float* qbuf = smf + A_Q;
    float* kT   = smf + A_KT;
    float* vbuf = smf + A_V;
    float* sbuf = smf + A_S;
    float* sbias = smf + A_BIAS;
    unsigned short* rel = (unsigned short*)(smf + A_REL);
    int* srcidx = (int*)(smf + A_SRC);
    float* wbuf = smf + A_WB;

    const int tid = threadIdx.x;
    const int wb = blockIdx.x;
    const int bb = wb >> 10;
    const int w  = wb & 1023;
    const int iw = w >> 8, xw = (w >> 4) & 15, tw = w & 15;

    // prefetch QKV weight chunk 0 (32 k-rows x 288 = 9216 floats; 18/thread)
    float2 pf[9];
    {
        const float* src = qkv_w + tid * 18;
        #pragma unroll
        for (int i = 0; i < 9; i++) pf[i] = __ldg((const float2*)(src + 2 * i));
    }

    if (tid < NW) {
        int i = tid >> 4, xx = (tid >> 2) & 3, tt = tid & 3;
        int gi = (iw * 4 + i  + 2) & 15;
        int gx = (xw * 4 + xx + 2) & 63;
        int gt = (tw * 4 + tt + 2) & 63;
        srcidx[tid] = ((gi << 6) + gx) * 64 + gt;
    }
    for (int p = tid; p < 4096; p += 512) {
        int n = p >> 6, m = p & 63;
        int di = (n >> 4)       - (m >> 4)       + 3;
        int dx = ((n >> 2) & 3) - ((m >> 2) & 3) + 3;
        int dt = (n & 3)        - (m & 3)        + 3;
        rel[p] = (unsigned short)((di * 7 + dx) * 7 + dt);
    }
    for (int i = tid; i < 343 * NH; i += 512) sbias[i] = __ldg(bias_table + i);
    __syncthreads();

    // ---- LN1 -> xdup[c][2n] dup pairs
    {
        const int n = tid >> 3, q8 = tid & 7;
        const float* xr = x + ((size_t)(bb * LTOK + srcidx[n])) * C + q8 * 12;
        float v[12]; float s = 0.f, ss = 0.f;
        #pragma unroll
        for (int j = 0; j < 12; j++) { float t = xr[j]; v[j] = t; s += t; ss += t * t; }
        s  += __shfl_xor_sync(0xffffffffu, s, 1);  ss += __shfl_xor_sync(0xffffffffu, ss, 1);
        s  += __shfl_xor_sync(0xffffffffu, s, 2);  ss += __shfl_xor_sync(0xffffffffu, ss, 2);
        s  += __shfl_xor_sync(0xffffffffu, s, 4);  ss += __shfl_xor_sync(0xffffffffu, ss, 4);
        float mean = s * (1.f / 96.f);
        float var  = ss * (1.f / 96.f) - mean * mean;
        float rstd = rsqrtf(var + 1e-5f);
        #pragma unroll
        for (int j = 0; j < 12; j++) {
            int c = q8 * 12 + j;
            float val = (v[j] - mean) * rstd * __ldg(g1 + c) + __ldg(b1 + c);
            stsb64(xdup + c * 130 + 2 * n, dup2(val));
        }
    }
    __syncthreads();

    // ---- QKV GEMM [64x96]@[96x288], 3 chunks of 32 k, weights via smem
    {
        const int rg = tid >> 5, lane = tid & 31;
        const int r0 = rg * 4;
        u64t acc[4][4]; float accs[4];
        #pragma unroll
        for (int j = 0; j < 4; j++) {
            float2 bv = __ldg((const float2*)(qkv_b + 2 * lane + 64 * j));
            u64t bj = pk2(bv.x, bv.y);
            #pragma unroll
            for (int r = 0; r < 4; r++) acc[r][j] = bj;
        }
        {
            float bs = __ldg(qkv_b + 256 + lane);
            #pragma unroll
            for (int r = 0; r < 4; r++) accs[r] = bs;
        }
        #pragma unroll 1
        for (int c = 0; c < 3; c++) {
            {   // commit staged chunk
                float* d = wbuf + tid * 18;
                #pragma unroll
                for (int i = 0; i < 9; i++) *(float2*)(d + 2 * i) = pf[i];
            }
            __syncthreads();
            if (c < 2) {
                const float* src = qkv_w + (c + 1) * 9216 + tid * 18;
                #pragma unroll
                for (int i = 0; i < 9; i++) pf[i] = __ldg((const float2*)(src + 2 * i));
            }
            #pragma unroll 2
            for (int kk = 0; kk < 32; kk++) {
                int k = 32 * c + kk;
                u64t ad[4];
                #pragma unroll
                for (int r = 0; r < 4; r++) ad[r] = ldsb64(xdup + k * 130 + 2 * (r0 + r));
                const float* wr = wbuf + kk * 288;
                #pragma unroll
                for (int j = 0; j < 4; j++) {
                    u64t wp = ldsb64(wr + 2 * lane + 64 * j);
                    #pragma unroll
                    for (int r = 0; r < 4; r++) fma2(acc[r][j], ad[r], wp);
                }
                float wsc = wr[256 + lane];
                #pragma unroll
                for (int r = 0; r < 4; r++) {
                    float av = up2(ad[r]).x;
                    accs[r] = fmaf(av, wsc, accs[r]);
                }
            }
            __syncthreads();
        }
        // scatter to qbuf / kT / vbuf
        #pragma unroll
        for (int r = 0; r < 4; r++) {
            int row = r0 + r;
            stsb64(qbuf + row * 100 + 2 * lane, acc[r][0]);
            {
                int c0 = 64 + 2 * lane;
                if (c0 < 96) {
                    stsb64(qbuf + row * 100 + c0, acc[r][1]);
                } else {
                    float2 t = up2(acc[r][1]);
                    int kc = c0 - 96;
                    kT[kc * 68 + row] = t.x;
                    kT[(kc + 1) * 68 + row] = t.y;
                }
            }
            {
                float2 t = up2(acc[r][2]);
                int kc = 32 + 2 * lane;
                kT[kc * 68 + row] = t.x;
                kT[(kc + 1) * 68 + row] = t.y;
            }
            stsb64(vbuf + row * 100 + 2 * lane, acc[r][3]);
            vbuf[row * 100 + 64 + lane] = accs[r];
        }
    }
    __syncthreads();

    float* oT = xdup;   // reuse

    // ---- attention (proven inner loops)
    {
        const int n = tid >> 3, sub = tid & 7;
        const int m0 = sub * 8;
        #pragma unroll 1
        for (int h = 0; h < NH; h++) {
            const int hb = h * HD;
            u64t qd[HD];
            #pragma unroll
            for (int dd = 0; dd < HD; dd++) qd[dd] = dup2(qbuf[n * 100 + hb + dd]);

            u64t p2[4] = {0ull, 0ull, 0ull, 0ull};
            #pragma unroll
            for (int dd = 0; dd < HD; dd++) {
                const float* kp = kT + (hb + dd) * 68 + m0;
                u64t k01, k23, k45, k67;
                ldsv2b64(k01, k23, kp);
                ldsv2b64(k45, k67, kp + 4);
                fma2(p2[0], qd[dd], k01); fma2(p2[1], qd[dd], k23);
                fma2(p2[2], qd[dd], k45); fma2(p2[3], qd[dd], k67);
            }
            float p[8];
            #pragma unroll
            for (int i = 0; i < 4; i++) { float2 t = up2(p2[i]); p[2*i] = t.x; p[2*i+1] = t.y; }
            #pragma unroll
            for (int i = 0; i < 8; i++) {
                int rdx = rel[n * 64 + m0 + i];
                p[i] = p[i] * 0.25f + sbias[rdx * NH + h];
            }
            float mx = -1e30f;
            #pragma unroll
            for (int i = 0; i < 8; i++) mx = fmaxf(mx, p[i]);
            mx = fmaxf(mx, __shfl_xor_sync(0xffffffffu, mx, 1));
            mx = fmaxf(mx, __shfl_xor_sync(0xffffffffu, mx, 2));
            mx = fmaxf(mx, __shfl_xor_sync(0xffffffffu, mx, 4));
            float sum = 0.f;
            #pragma unroll
            for (int i = 0; i < 8; i++) { p[i] = __expf(p[i] - mx); sum += p[i]; }
            sum += __shfl_xor_sync(0xffffffffu, sum, 1);
            sum += __shfl_xor_sync(0xffffffffu, sum, 2);
            sum += __shfl_xor_sync(0xffffffffu, sum, 4);
            float inv = 1.f / sum;
            #pragma unroll
            for (int i = 0; i < 8; i++) sbuf[n * 68 + m0 + i] = p[i] * inv;
            __syncwarp();

            float o0 = 0.f, o1 = 0.f, o0b = 0.f, o1b = 0.f;
            const float* vb = vbuf + hb + sub * 2;
            #pragma unroll
            for (int m4 = 0; m4 < 16; m4++) {
                float4 pr = ldsf4(sbuf + n * 68 + m4 * 4);
                const float* vm = vb + (m4 * 4) * 100;
                float2 v0 = ldsf2(vm);         o0  += pr.x * v0.x; o1  += pr.x * v0.y;
                float2 v1 = ldsf2(vm + 100);   o0b += pr.y * v1.x; o1b += pr.y * v1.y;
                float2 v2 = ldsf2(vm + 200);   o0  += pr.z * v2.x; o1  += pr.z * v2.y;
                float2 v3 = ldsf2(vm + 300);   o0b += pr.w * v3.x; o1b += pr.w * v3.y;
            }
            oT[(hb + sub * 2) * 68 + n]     = o0 + o0b;
            oT[(hb + sub * 2 + 1) * 68 + n] = o1 + o1b;
            __syncwarp();
        }
    }
    __syncthreads();

    // ---- stage proj_w into smem (one shot)
    {
        const float* src = proj_w + tid * 18;
        float2 t[9];
        #pragma unroll
        for (int i = 0; i < 9; i++) t[i] = __ldg((const float2*)(src + 2 * i));
        float* d = wbuf + tid * 18;
        #pragma unroll
        for (int i = 0; i < 9; i++) *(float2*)(d + 2 * i) = t[i];
    }
    __syncthreads();

    // ---- proj [64x96]@[96x96], split-K 2, weights from smem + residual
    {
        const int kh = tid >> 8;
        const int t2 = tid & 255;
        const int rg = t2 >> 5, lane = t2 & 31;
        const int r0 = rg * 8;
        u64t acc[4][3];
        #pragma unroll
        for (int j = 0; j < 3; j++) {
            u64t bj = (kh == 0) ? dup2(__ldg(proj_b + lane + 32 * j)) : 0ull;
            #pragma unroll
            for (int p = 0; p < 4; p++) acc[p][j] = bj;
        }
        const int k0 = kh * 48;
        #pragma unroll 2
        for (int kk = 0; kk < 48; kk++) {
            int k = k0 + kk;
            u64t a[4];
            ldsv2b64(a[0], a[1], oT + k * 68 + r0);
            ldsv2b64(a[2], a[3], oT + k * 68 + r0 + 4);
            const float* wr = wbuf + k * 96 + lane;
            #pragma unroll
            for (int j = 0; j < 3; j++) {
                u64t wd = dup2(wr[32 * j]);
                #pragma unroll
                for (int p = 0; p < 4; p++) fma2(acc[p][j], a[p], wd);
            }
        }
        float* red = qbuf;   // [64][98]
        if (kh == 1) {
            #pragma unroll
            for (int p = 0; p < 4; p++) {
                int r = r0 + 2 * p;
                #pragma unroll
                for (int j = 0; j < 3; j++) {
                    int c = lane + 32 * j;
                    float2 t = up2(acc[p][j]);
                    red[r * 98 + c] = t.x;
                    red[(r + 1) * 98 + c] = t.y;
                }
            }
        }
        __syncthreads();
        if (kh == 0) {
            #pragma unroll
            for (int p = 0; p < 4; p++) {
                int r = r0 + 2 * p;
                size_t b0 = (size_t)(bb * LTOK + srcidx[r]) * C;
                size_t b1 = (size_t)(bb * LTOK + srcidx[r + 1]) * C;
                #pragma unroll
                for (int j = 0; j < 3; j++) {
                    int c = lane + 32 * j;
                    float2 t = up2(acc[p][j]);
                    g_ybuf[b0 + c] = x[b0 + c] + t.x + red[r * 98 + c];
                    g_ybuf[b1 + c] = x[b1 + c] + t.y + red[(r + 1) * 98 + c];
                }
            }
        }
    }
}

// ===========================================================================
// Kernel B: LN2 + MLP, weight chunks staged in smem with reg prefetch
// ===========================================================================
#define B_HID 0        // hidT [384][68]
#define B_H2D 26112    // h2dup [96][130]
#define B_WB  38592    // weight chunk buf [12288]
#define B_TOT 50880

__global__ __launch_bounds__(512, 1)
void mlp_kernel(const float* __restrict__ g2, const float* __restrict__ b2,
                const float* __restrict__ w1, const float* __restrict__ bb1,
                const float* __restrict__ w2, const float* __restrict__ bb2,
                float* __restrict__ out)
{
    extern __shared__ float smf[];
    float* hidT  = smf + B_HID;
    float* h2dup = smf + B_H2D;
    float* wbuf  = smf + B_WB;

    const int tid = threadIdx.x;
    const int t0 = blockIdx.x * NW;

    // prefetch w1 chunk 0 (32 k-rows x 384 = 12288 floats; 24/thread)
    float4 pf1[6];
    {
        const float* src = w1 + tid * 24;
        #pragma unroll
        for (int i = 0; i < 6; i++) pf1[i] = __ldg((const float4*)(src + 4 * i));
    }

    // ---- LN2 -> h2dup[c][2n] dup pairs
    {
        const int n = tid >> 3, q8 = tid & 7;
        const float* yr = g_ybuf + (size_t)(t0 + n) * C + q8 * 12;
        float v[12]; float s = 0.f, ss = 0.f;
        #pragma unroll
        for (int j = 0; j < 12; j++) { float t = yr[j]; v[j] = t; s += t; ss += t * t; }
        s  += __shfl_xor_sync(0xffffffffu, s, 1);  ss += __shfl_xor_sync(0xffffffffu, ss, 1);
        s  += __shfl_xor_sync(0xffffffffu, s, 2);  ss += __shfl_xor_sync(0xffffffffu, ss, 2);
        s  += __shfl_xor_sync(0xffffffffu, s, 4);  ss += __shfl_xor_sync(0xffffffffu, ss, 4);
        float mean = s * (1.f / 96.f);
        float var  = ss * (1.f / 96.f) - mean * mean;
        float rstd = rsqrtf(var + 1e-5f);
        #pragma unroll
        for (int j = 0; j < 12; j++) {
            int c = q8 * 12 + j;
            float val = (v[j] - mean) * rstd * __ldg(g2 + c) + __ldg(b2 + c);
            stsb64(h2dup + c * 130 + 2 * n, dup2(val));
        }
    }
    __syncthreads();

    // ---- GEMM1 [64x96]@[96x384] + GELU -> hidT[c][n], 3 chunks of 32 k
    {
        const int rg = tid >> 5, lane = tid & 31;
        const int r0 = rg * 4;
        u64t acc[4][6];
        #pragma unroll
        for (int j = 0; j < 6; j++) {
            float2 bv = __ldg((const float2*)(bb1 + 2 * lane + 64 * j));
            u64t bj = pk2(bv.x, bv.y);
            #pragma unroll
            for (int r = 0; r < 4; r++) acc[r][j] = bj;
        }
        #pragma unroll 1
        for (int c = 0; c < 3; c++) {
            {
                float* d = wbuf + tid * 24;
                #pragma unroll
                for (int i = 0; i < 6; i++) *(float4*)(d + 4 * i) = pf1[i];
            }
            __syncthreads();
            if (c < 2) {
                const float* src = w1 + (c + 1) * 12288 + tid * 24;
                #pragma unroll
                for (int i = 0; i < 6; i++) pf1[i] = __ldg((const float4*)(src + 4 * i));
            }
            #pragma unroll 2
            for (int kk = 0; kk < 32; kk++) {
                int k = 32 * c + kk;
                u64t ad[4];
                #pragma unroll
                for (int r = 0; r < 4; r++) ad[r] = ldsb64(h2dup + k * 130 + 2 * (r0 + r));
                const float* wr = wbuf + kk * 384;
                #pragma unroll
                for (int j = 0; j < 6; j++) {
                    u64t wp = ldsb64(wr + 2 * lane + 64 * j);
                    #pragma unroll
                    for (int r = 0; r < 4; r++) fma2(acc[r][j], ad[r], wp);
                }
            }
            __syncthreads();
        }
        // GELU + store hidT
        #pragma unroll
        for (int r = 0; r < 4; r++) {
            int row = r0 + r;
            #pragma unroll
            for (int j = 0; j < 6; j++) {
                int cc = 2 * lane + 64 * j;
                float2 t = up2(acc[r][j]);
                float gx = 0.5f * t.x * (1.0f + erff(t.x * 0.70710678118654752f));
                float gy = 0.5f * t.y * (1.0f + erff(t.y * 0.70710678118654752f));
                hidT[cc * 68 + row] = gx;
                hidT[(cc + 1) * 68 + row] = gy;
            }
        }
    }

    // ---- GEMM2 [64x384]@[384x96], 6 chunks of 64 k, w2 staged DUP'd in smem
    {
        const int rg = tid >> 5, lane = tid & 31;
        const int r0 = rg * 4;
        const int skk = tid >> 3, scol = (tid & 7) * 12;   // staging coords
        u64t acc[2][3];
        #pragma unroll
        for (int j = 0; j < 3; j++) {
            u64t bj = dup2(__ldg(bb2 + lane + 32 * j));
            acc[0][j] = bj; acc[1][j] = bj;
        }
        // prefetch w2 chunk 0 (64 k x 96 = 6144 floats; 12/thread)
        float4 pf2[3];
        {
            const float* src = w2 + tid * 12;
            #pragma unroll
            for (int i = 0; i < 3; i++) pf2[i] = __ldg((const float4*)(src + 4 * i));
        }
        #pragma unroll 1
        for (int c = 0; c < 6; c++) {
            {   // stage dup'd: wbuf[kk][2*col] = (v,v)
                const float* pv = (const float*)pf2;
                float* d = wbuf + skk * 192 + 2 * scol;
                #pragma unroll
                for (int i = 0; i < 12; i++) stsb64(d + 2 * i, dup2(pv[i]));
            }
            __syncthreads();   // also orders hidT stores (c==0) for readers
            if (c < 5) {
                const float* src = w2 + (c + 1) * 6144 + tid * 12;
                #pragma unroll
                for (int i = 0; i < 3; i++) pf2[i] = __ldg((const float4*)(src + 4 * i));
            }
            #pragma unroll 2
            for (int kk = 0; kk < 64; kk++) {
                int k = 64 * c + kk;
                u64t a0, a1;
                ldsv2b64(a0, a1, hidT + k * 68 + r0);
                const float* wr = wbuf + kk * 192 + 2 * lane;
                #pragma unroll
                for (int j = 0; j < 3; j++) {
                    u64t wd = ldsb64(wr + 64 * j);
                    fma2(acc[0][j], a0, wd);
                    fma2(acc[1][j], a1, wd);
                }
            }
            __syncthreads();
        }
        // epilogue: residual + store
        #pragma unroll
        for (int p = 0; p < 2; p++) {
            int r = r0 + 2 * p;
            size_t b0 = (size_t)(t0 + r) * C;
            size_t b1 = (size_t)(t0 + r + 1) * C;
            #pragma unroll
            for (int j = 0; j < 3; j++) {
                int cc = lane + 32 * j;
                float2 t = up2(acc[p][j]);
                out[b0 + cc] = g_ybuf[b0 + cc] + t.x;
                out[b1 + cc] = g_ybuf[b1 + cc] + t.y;
            }
        }
    }
}

// ---------------------------------------------------------------------------
extern "C" void kernel_launch(void* const* d_in, const int* in_sizes, int n_in,
                              void* d_out, int out_size)
{
    const float* x        = (const float*)d_in[0];
    const float* norm1_g  = (const float*)d_in[1];
    const float* norm1_b  = (const float*)d_in[2];
    const float* qkv_w    = (const float*)d_in[3];
    const float* qkv_b    = (const float*)d_in[4];
    const float* proj_w   = (const float*)d_in[5];
    const float* proj_b   = (const float*)d_in[6];
    const float* bias_tab = (const float*)d_in[7];
    const float* norm2_g  = (const float*)d_in[8];
    const float* norm2_b  = (const float*)d_in[9];
    const float* mlp_w1   = (const float*)d_in[10];
    const float* mlp_b1   = (const float*)d_in[11];
    const float* mlp_w2   = (const float*)d_in[12];
    const float* mlp_b2   = (const float*)d_in[13];
    float* out = (float*)d_out;

    cudaFuncSetAttribute(win_attn_kernel,
                         cudaFuncAttributeMaxDynamicSharedMemorySize, A_TOT * 4);
    cudaFuncSetAttribute(mlp_kernel,
                         cudaFuncAttributeMaxDynamicSharedMemorySize, B_TOT * 4);

    win_attn_kernel<<<NTILE, 512, A_TOT * 4>>>(x, norm1_g, norm1_b,
                                               qkv_w, qkv_b, proj_w, proj_b,
                                               bias_tab);
    mlp_kernel<<<NTILE, 512, B_TOT * 4>>>(norm2_g, norm2_b,
                                          mlp_w1, mlp_b1, mlp_w2, mlp_b2, out);
}